// round 2
// baseline (speedup 1.0000x reference)
#include <cuda_runtime.h>

#define BB   2048
#define SS   16
#define AA   16
#define DSZ  128
#define DAZ  128
#define HH   64
#define BT   128
#define XSTR 132   // padded X row stride (floats)
#define HSTR 68    // padded H row stride (floats)

#define SMEM_FLOATS (BT*XSTR + DAZ*HH + HH*HH + HH*DSZ + 2*BT*HSTR + 2*HH)
#define SMEM_BYTES  (SMEM_FLOATS * 4)

__device__ int g_mask[SS * AA];

static __device__ __forceinline__ unsigned long long dup2(float x) {
    unsigned long long r;
    asm("mov.b64 %0, {%1, %1};" : "=l"(r) : "f"(x));
    return r;
}
static __device__ __forceinline__ unsigned long long fma2(unsigned long long a,
                                                          unsigned long long b,
                                                          unsigned long long c) {
    unsigned long long d;
    asm("fma.rn.f32x2 %0, %1, %2, %3;" : "=l"(d) : "l"(a), "l"(b), "l"(c));
    return d;
}
static __device__ __forceinline__ float2 upk2(unsigned long long v) {
    float lo, hi;
    asm("mov.b64 {%0, %1}, %2;" : "=f"(lo), "=f"(hi) : "l"(v));
    return make_float2(lo, hi);
}

// causal_relation arrives as bool(1B), int32, or float32 depending on harness
// dtype mapping. Sniff the byte pattern (first 256 bytes are valid in every
// case) and build a canonical int mask. Deterministic: recomputed every launch.
__global__ void build_mask_kernel(const unsigned char* __restrict__ raw) {
    if (threadIdx.x != 0) return;
    bool off_zero = true;                       // int32: bytes at i%4!=0 are 0
    for (int i = 0; i < SS * AA; i++)
        if ((i & 3) && raw[i]) { off_zero = false; break; }
    if (off_zero) {
        const int* p = (const int*)raw;
        for (int i = 0; i < SS * AA; i++) g_mask[i] = (p[i] != 0);
        return;
    }
    const unsigned int* f = (const unsigned int*)raw;   // float32: 0.0f / 1.0f
    bool isf = true;
    for (int i = 0; i < 64; i++) {
        unsigned v = f[i];
        if (v != 0u && v != 0x3f800000u) { isf = false; break; }
    }
    if (isf) {
        for (int i = 0; i < SS * AA; i++) g_mask[i] = (f[i] != 0u);
        return;
    }
    for (int i = 0; i < SS * AA; i++) g_mask[i] = (raw[i] != 0);  // bool 1B
}

__global__ void __launch_bounds__(256, 1)
intervention_kernel(const float* __restrict__ state,
                    const float* __restrict__ act,
                    const float* __restrict__ W1g,
                    const float* __restrict__ b1g,
                    const float* __restrict__ W2g,
                    const float* __restrict__ b2g,
                    const float* __restrict__ W3g,
                    const float* __restrict__ b3g,
                    float* __restrict__ out) {
    extern __shared__ float sm[];
    float* sX  = sm;                     // [BT][XSTR]
    float* sW1 = sX  + BT * XSTR;        // [DAZ][HH]  (flat copy)
    float* sW2 = sW1 + DAZ * HH;         // [HH][HH]
    float* sW3 = sW2 + HH * HH;          // [HH][DSZ]
    float* sH1 = sW3 + HH * DSZ;         // [BT][HSTR]
    float* sH2 = sH1 + BT * HSTR;        // [BT][HSTR]
    float* sB1 = sH2 + BT * HSTR;        // [HH]
    float* sB2 = sB1 + HH;               // [HH]

    const int tid = threadIdx.x;
    const int s   = blockIdx.y;
    const int b0  = blockIdx.x * BT;

    const int r0 = (tid >> 3) * 4;       // 4 batch rows per thread (all layers)
    const int c0 = (tid & 7) * 8;        // layer1/2: 8 of 64 hidden cols
    const int e0 = (tid & 7) * 16;       // layer3: 16 of 128 output cols

    float acc[4][16];                    // persistent masked-sum accumulator
    #pragma unroll
    for (int i = 0; i < 4; i++)
        #pragma unroll
        for (int j = 0; j < 16; j++) acc[i][j] = 0.f;

    for (int a = 0; a < AA; a++) {
        if (!g_mask[s * AA + a]) continue;        // uniform across CTA
        __syncthreads();                          // prev layer3 readers done

        const int sa = s * AA + a;
        const float* Wa1 = W1g + (size_t)sa * (DAZ * HH);
        const float* Wa2 = W2g + (size_t)sa * (HH * HH);
        const float* Wa3 = W3g + (size_t)sa * (HH * DSZ);

        // ---- cooperative loads -------------------------------------------
        for (int idx = tid; idx < BT * DAZ / 4; idx += 256) {
            int row = idx >> 5, kq = idx & 31;
            float4 v = *(const float4*)(act + ((size_t)(b0 + row) * AA + a) * DAZ + kq * 4);
            *(float4*)(sX + row * XSTR + kq * 4) = v;
        }
        for (int idx = tid; idx < DAZ * HH / 4; idx += 256)
            *(float4*)(sW1 + idx * 4) = *(const float4*)(Wa1 + idx * 4);
        for (int idx = tid; idx < HH * HH / 4; idx += 256)
            *(float4*)(sW2 + idx * 4) = *(const float4*)(Wa2 + idx * 4);
        for (int idx = tid; idx < HH * DSZ / 4; idx += 256)
            *(float4*)(sW3 + idx * 4) = *(const float4*)(Wa3 + idx * 4);
        if (tid < HH) {
            sB1[tid] = b1g[(size_t)sa * HH + tid];
            sB2[tid] = b2g[(size_t)sa * HH + tid];
        }
        __syncthreads();

        // ---- layer 1: H1 = relu(X @ W1 + b1), K = 128 --------------------
        {
            unsigned long long ap[4][4];
            #pragma unroll
            for (int i = 0; i < 4; i++)
                #pragma unroll
                for (int j = 0; j < 4; j++) ap[i][j] = 0ull;
            for (int k = 0; k < DAZ; k += 4) {
                float xs[4][4];
                #pragma unroll
                for (int i = 0; i < 4; i++) {
                    float4 t = *(const float4*)(sX + (r0 + i) * XSTR + k);
                    xs[i][0] = t.x; xs[i][1] = t.y; xs[i][2] = t.z; xs[i][3] = t.w;
                }
                #pragma unroll
                for (int kk = 0; kk < 4; kk++) {
                    unsigned long long w[4];
                    #pragma unroll
                    for (int j = 0; j < 4; j++)
                        w[j] = *(const unsigned long long*)(sW1 + (k + kk) * HH + c0 + j * 2);
                    #pragma unroll
                    for (int i = 0; i < 4; i++) {
                        unsigned long long xd = dup2(xs[i][kk]);
                        #pragma unroll
                        for (int j = 0; j < 4; j++) ap[i][j] = fma2(xd, w[j], ap[i][j]);
                    }
                }
            }
            #pragma unroll
            for (int i = 0; i < 4; i++)
                #pragma unroll
                for (int j = 0; j < 4; j++) {
                    float2 v = upk2(ap[i][j]);
                    int c = c0 + 2 * j;
                    float2 h;
                    h.x = fmaxf(v.x + sB1[c],     0.f);
                    h.y = fmaxf(v.y + sB1[c + 1], 0.f);
                    *(float2*)(sH1 + (r0 + i) * HSTR + c) = h;
                }
        }
        __syncthreads();

        // ---- layer 2: H2 = relu(H1 @ W2 + b2), K = 64 --------------------
        {
            unsigned long long ap[4][4];
            #pragma unroll
            for (int i = 0; i < 4; i++)
                #pragma unroll
                for (int j = 0; j < 4; j++) ap[i][j] = 0ull;
            for (int k = 0; k < HH; k += 4) {
                float xs[4][4];
                #pragma unroll
                for (int i = 0; i < 4; i++) {
                    float4 t = *(const float4*)(sH1 + (r0 + i) * HSTR + k);
                    xs[i][0] = t.x; xs[i][1] = t.y; xs[i][2] = t.z; xs[i][3] = t.w;
                }
                #pragma unroll
                for (int kk = 0; kk < 4; kk++) {
                    unsigned long long w[4];
                    #pragma unroll
                    for (int j = 0; j < 4; j++)
                        w[j] = *(const unsigned long long*)(sW2 + (k + kk) * HH + c0 + j * 2);
                    #pragma unroll
                    for (int i = 0; i < 4; i++) {
                        unsigned long long xd = dup2(xs[i][kk]);
                        #pragma unroll
                        for (int j = 0; j < 4; j++) ap[i][j] = fma2(xd, w[j], ap[i][j]);
                    }
                }
            }
            #pragma unroll
            for (int i = 0; i < 4; i++)
                #pragma unroll
                for (int j = 0; j < 4; j++) {
                    float2 v = upk2(ap[i][j]);
                    int c = c0 + 2 * j;
                    float2 h;
                    h.x = fmaxf(v.x + sB2[c],     0.f);
                    h.y = fmaxf(v.y + sB2[c + 1], 0.f);
                    *(float2*)(sH2 + (r0 + i) * HSTR + c) = h;
                }
        }
        __syncthreads();

        // ---- layer 3: acc += relu(H2 @ W3 + b3), K = 64 ------------------
        {
            const float* b3a = b3g + (size_t)sa * DSZ;
            #pragma unroll
            for (int ch = 0; ch < 2; ch++) {
                unsigned long long tp[4][4];
                #pragma unroll
                for (int i = 0; i < 4; i++)
                    #pragma unroll
                    for (int j = 0; j < 4; j++) tp[i][j] = 0ull;
                for (int k = 0; k < HH; k += 4) {
                    float hs[4][4];
                    #pragma unroll
                    for (int i = 0; i < 4; i++) {
                        float4 t = *(const float4*)(sH2 + (r0 + i) * HSTR + k);
                        hs[i][0] = t.x; hs[i][1] = t.y; hs[i][2] = t.z; hs[i][3] = t.w;
                    }
                    #pragma unroll
                    for (int kk = 0; kk < 4; kk++) {
                        unsigned long long w[4];
                        #pragma unroll
                        for (int j = 0; j < 4; j++)
                            w[j] = *(const unsigned long long*)(sW3 + (k + kk) * DSZ + e0 + ch * 8 + 2 * j);
                        #pragma unroll
                        for (int i = 0; i < 4; i++) {
                            unsigned long long xd = dup2(hs[i][kk]);
                            #pragma unroll
                            for (int j = 0; j < 4; j++) tp[i][j] = fma2(xd, w[j], tp[i][j]);
                        }
                    }
                }
                #pragma unroll
                for (int i = 0; i < 4; i++)
                    #pragma unroll
                    for (int j = 0; j < 4; j++) {
                        float2 v = upk2(tp[i][j]);
                        int e = e0 + ch * 8 + 2 * j;
                        acc[i][ch * 8 + 2 * j]     += fmaxf(v.x + __ldg(b3a + e),     0.f);
                        acc[i][ch * 8 + 2 * j + 1] += fmaxf(v.y + __ldg(b3a + e + 1), 0.f);
                    }
            }
        }
    }

    // ---- epilogue: out = state + diff ------------------------------------
    #pragma unroll
    for (int i = 0; i < 4; i++) {
        size_t base = ((size_t)(b0 + r0 + i) * SS + s) * DSZ + e0;
        #pragma unroll
        for (int q = 0; q < 4; q++) {
            float4 sv = *(const float4*)(state + base + q * 4);
            float4 ov;
            ov.x = sv.x + acc[i][q * 4 + 0];
            ov.y = sv.y + acc[i][q * 4 + 1];
            ov.z = sv.z + acc[i][q * 4 + 2];
            ov.w = sv.w + acc[i][q * 4 + 3];
            *(float4*)(out + base + q * 4) = ov;
        }
    }
}

extern "C" void kernel_launch(void* const* d_in, const int* in_sizes, int n_in,
                              void* d_out, int out_size) {
    const float* state = (const float*)d_in[0];
    const float* act   = (const float*)d_in[1];
    const unsigned char* mask_raw = (const unsigned char*)d_in[2];
    const float* W1 = (const float*)d_in[3];
    const float* b1 = (const float*)d_in[4];
    const float* W2 = (const float*)d_in[5];
    const float* b2 = (const float*)d_in[6];
    const float* W3 = (const float*)d_in[7];
    const float* b3 = (const float*)d_in[8];
    float* out = (float*)d_out;

    (void)in_sizes; (void)n_in; (void)out_size;

    build_mask_kernel<<<1, 32>>>(mask_raw);

    cudaFuncSetAttribute(intervention_kernel,
                         cudaFuncAttributeMaxDynamicSharedMemorySize, SMEM_BYTES);
    dim3 grid(BB / BT, SS);
    intervention_kernel<<<grid, 256, SMEM_BYTES>>>(state, act, W1, b1, W2, b2,
                                                   W3, b3, out);
}

// round 8
// speedup vs baseline: 3.9403x; 3.9403x over previous
#include <cuda_runtime.h>
#include <cstdint>

#define BB   2048
#define SS   16
#define AA   16
#define DSZ  128
#define DAZ  128
#define HH   64
#define BT   64

// ---------------- global bf16 images (prologue output) ---------------------
// X planes: [b][a][k] bf16, hi and lo
__device__ __align__(16) unsigned short g_xhi[BB * AA * DAZ];
__device__ __align__(16) unsigned short g_xlo[BB * AA * DAZ];
// Weight planes, transposed to [n][k] with k padded to K+8 bf16 per row:
// W1: [2 planes][64 n][136] (= 34816 B/sa), W2: [2][64][72] (18432 B),
// W3: [2][128][72] (36864 B). hi plane first, lo at +plane_bytes.
__device__ __align__(16) unsigned char g_w1img[SS * AA * 34816];
__device__ __align__(16) unsigned char g_w2img[SS * AA * 18432];
__device__ __align__(16) unsigned char g_w3img[SS * AA * 36864];
__device__ __align__(16) float g_bias[SS * AA * 256];   // [0,64):b1 [64,128):b2 [128,256):b3
__device__ int g_mask[SS * AA];

// ---------------- helpers ---------------------------------------------------
static __device__ __forceinline__ uint32_t smem_u32(const void* p) {
    uint32_t a;
    asm("{ .reg .u64 t; cvta.to.shared.u64 t, %1; cvt.u32.u64 %0, t; }" : "=r"(a) : "l"(p));
    return a;
}
static __device__ __forceinline__ unsigned short f2bf(float x) {
    unsigned short h;
    asm("cvt.rn.bf16.f32 %0, %1;" : "=h"(h) : "f"(x));
    return h;
}
static __device__ __forceinline__ float bf2f(unsigned short h) {
    return __uint_as_float(((unsigned)h) << 16);
}
static __device__ __forceinline__ unsigned packbf(unsigned short lo, unsigned short hi) {
    return (unsigned)lo | ((unsigned)hi << 16);
}
// D += A x B  (m16n8k16, bf16 in, f32 acc)
static __device__ __forceinline__ void mma_bf16(float* c, const unsigned* a, const unsigned* b) {
    asm volatile("mma.sync.aligned.m16n8k16.row.col.f32.bf16.bf16.f32 "
                 "{%0,%1,%2,%3}, {%4,%5,%6,%7}, {%8,%9}, {%0,%1,%2,%3};"
                 : "+f"(c[0]), "+f"(c[1]), "+f"(c[2]), "+f"(c[3])
                 : "r"(a[0]), "r"(a[1]), "r"(a[2]), "r"(a[3]), "r"(b[0]), "r"(b[1]));
}
static __device__ __forceinline__ void ldsm4(unsigned* r, uint32_t addr) {
    asm volatile("ldmatrix.sync.aligned.m8n8.x4.shared.b16 {%0,%1,%2,%3}, [%4];"
                 : "=r"(r[0]), "=r"(r[1]), "=r"(r[2]), "=r"(r[3]) : "r"(addr));
}
#define CP16(sdst, gsrc) asm volatile("cp.async.cg.shared.global [%0], [%1], 16;" :: "r"(sdst), "l"(gsrc))
#define CP_COMMIT()      asm volatile("cp.async.commit_group;" ::: "memory")
#define CP_WAIT(n)       asm volatile("cp.async.wait_group %0;" :: "n"(n) : "memory")

// ---------------- prologue: mask -------------------------------------------
__global__ void build_mask_kernel(const unsigned char* __restrict__ raw) {
    if (threadIdx.x != 0) return;
    bool off_zero = true;
    for (int i = 0; i < SS * AA; i++)
        if ((i & 3) && raw[i]) { off_zero = false; break; }
    if (off_zero) {
        const int* p = (const int*)raw;
        for (int i = 0; i < SS * AA; i++) g_mask[i] = (p[i] != 0);
        return;
    }
    const unsigned int* f = (const unsigned int*)raw;
    bool isf = true;
    for (int i = 0; i < 64; i++) {
        unsigned v = f[i];
        if (v != 0u && v != 0x3f800000u) { isf = false; break; }
    }
    if (isf) {
        for (int i = 0; i < SS * AA; i++) g_mask[i] = (f[i] != 0u);
        return;
    }
    for (int i = 0; i < SS * AA; i++) g_mask[i] = (raw[i] != 0);
}

// ---------------- prologue: X -> bf16 hi/lo planes --------------------------
__global__ void __launch_bounds__(256) conv_x_kernel(const float* __restrict__ act) {
    size_t idx = ((size_t)blockIdx.x * 256 + threadIdx.x) * 8;
    float4 v0 = *(const float4*)(act + idx);
    float4 v1 = *(const float4*)(act + idx + 4);
    float vv[8] = {v0.x, v0.y, v0.z, v0.w, v1.x, v1.y, v1.z, v1.w};
    unsigned short hb[8], lb[8];
    #pragma unroll
    for (int j = 0; j < 8; j++) {
        hb[j] = f2bf(vv[j]);
        lb[j] = f2bf(vv[j] - bf2f(hb[j]));
    }
    uint4 qh, ql;
    qh.x = packbf(hb[0], hb[1]); qh.y = packbf(hb[2], hb[3]);
    qh.z = packbf(hb[4], hb[5]); qh.w = packbf(hb[6], hb[7]);
    ql.x = packbf(lb[0], lb[1]); ql.y = packbf(lb[2], lb[3]);
    ql.z = packbf(lb[4], lb[5]); ql.w = packbf(lb[6], lb[7]);
    *(uint4*)(g_xhi + idx) = qh;
    *(uint4*)(g_xlo + idx) = ql;
}

// ---------------- prologue: weights -> [n][k+pad] hi/lo planes --------------
__global__ void __launch_bounds__(128) conv_w_kernel(const float* __restrict__ W1g,
                                                     const float* __restrict__ W2g,
                                                     const float* __restrict__ W3g,
                                                     const float* __restrict__ b1g,
                                                     const float* __restrict__ b2g,
                                                     const float* __restrict__ b3g) {
    const int sa = blockIdx.x;
    const int tid = threadIdx.x;

    // W1 [128 k][64 n] -> [64 n][136 k] hi/lo
    {
        const float* w = W1g + (size_t)sa * (DAZ * HH);
        unsigned char* img = g_w1img + (size_t)sa * 34816;
        for (int i = tid; i < 16 * 64; i += 128) {
            int c8 = i >> 6, n = i & 63;
            unsigned short hb[8], lb[8];
            #pragma unroll
            for (int j = 0; j < 8; j++) {
                float x = w[(c8 * 8 + j) * HH + n];
                hb[j] = f2bf(x);
                lb[j] = f2bf(x - bf2f(hb[j]));
            }
            uint4 qh, ql;
            qh.x = packbf(hb[0], hb[1]); qh.y = packbf(hb[2], hb[3]);
            qh.z = packbf(hb[4], hb[5]); qh.w = packbf(hb[6], hb[7]);
            ql.x = packbf(lb[0], lb[1]); ql.y = packbf(lb[2], lb[3]);
            ql.z = packbf(lb[4], lb[5]); ql.w = packbf(lb[6], lb[7]);
            *(uint4*)(img + n * 272 + c8 * 16)         = qh;
            *(uint4*)(img + 17408 + n * 272 + c8 * 16) = ql;
        }
    }
    // W2 [64 k][64 n] -> [64 n][72 k] hi/lo
    {
        const float* w = W2g + (size_t)sa * (HH * HH);
        unsigned char* img = g_w2img + (size_t)sa * 18432;
        for (int i = tid; i < 8 * 64; i += 128) {
            int c8 = i >> 6, n = i & 63;
            unsigned short hb[8], lb[8];
            #pragma unroll
            for (int j = 0; j < 8; j++) {
                float x = w[(c8 * 8 + j) * HH + n];
                hb[j] = f2bf(x);
                lb[j] = f2bf(x - bf2f(hb[j]));
            }
            uint4 qh, ql;
            qh.x = packbf(hb[0], hb[1]); qh.y = packbf(hb[2], hb[3]);
            qh.z = packbf(hb[4], hb[5]); qh.w = packbf(hb[6], hb[7]);
            ql.x = packbf(lb[0], lb[1]); ql.y = packbf(lb[2], lb[3]);
            ql.z = packbf(lb[4], lb[5]); ql.w = packbf(lb[6], lb[7]);
            *(uint4*)(img + n * 144 + c8 * 16)        = qh;
            *(uint4*)(img + 9216 + n * 144 + c8 * 16) = ql;
        }
    }
    // W3 [64 k][128 n] -> [128 n][72 k] hi/lo
    {
        const float* w = W3g + (size_t)sa * (HH * DSZ);
        unsigned char* img = g_w3img + (size_t)sa * 36864;
        for (int i = tid; i < 8 * 128; i += 128) {
            int c8 = i >> 7, n = i & 127;
            unsigned short hb[8], lb[8];
            #pragma unroll
            for (int j = 0; j < 8; j++) {
                float x = w[(c8 * 8 + j) * DSZ + n];
                hb[j] = f2bf(x);
                lb[j] = f2bf(x - bf2f(hb[j]));
            }
            uint4 qh, ql;
            qh.x = packbf(hb[0], hb[1]); qh.y = packbf(hb[2], hb[3]);
            qh.z = packbf(hb[4], hb[5]); qh.w = packbf(hb[6], hb[7]);
            ql.x = packbf(lb[0], lb[1]); ql.y = packbf(lb[2], lb[3]);
            ql.z = packbf(lb[4], lb[5]); ql.w = packbf(lb[6], lb[7]);
            *(uint4*)(img + n * 144 + c8 * 16)         = qh;
            *(uint4*)(img + 18432 + n * 144 + c8 * 16) = ql;
        }
    }
    // biases
    if (tid < 64) {
        g_bias[sa * 256 + tid]      = b1g[(size_t)sa * HH + tid];
        g_bias[sa * 256 + 64 + tid] = b2g[(size_t)sa * HH + tid];
    }
    if (tid < 128)
        g_bias[sa * 256 + 128 + tid] = b3g[(size_t)sa * DSZ + tid];
}

// ---------------- main kernel ----------------------------------------------
#define OFF_W1   0
#define OFF_W2   34816
#define OFF_W3   53248
#define OFF_BIAS 90112
#define SMEM_MAIN 91136

__global__ void __launch_bounds__(128, 2)
intervention_hmma_kernel(const float* __restrict__ state,
                         float* __restrict__ out) {
    extern __shared__ char sm[];
    const uint32_t smb = smem_u32(sm);
    const float* sBias = (const float*)(sm + OFF_BIAS);

    const int tid  = threadIdx.x;
    const int warp = tid >> 5;
    const int lane = tid & 31;
    const int s    = blockIdx.y;
    const int b0   = blockIdx.x * BT;

    const int rowbase = warp * 16;                 // this warp's 16 batch rows
    const int kb      = (lane & 3) * 2;            // A-frag k offset within 8
    const int rowadj  = (lane & 7) + ((lane & 16) ? 8 : 0);   // ldmatrix row
    const int coladj  = (lane & 8) ? 16 : 0;                  // ldmatrix col bytes
    const int r_lo    = b0 + rowbase + (lane >> 2);           // global batch row
    const uint32_t w1b = smb + OFF_W1;
    const uint32_t w2b = smb + OFF_W2;
    const uint32_t w3b = smb + OFF_W3;

    float acc[16][4];
    #pragma unroll
    for (int g = 0; g < 16; g++)
        #pragma unroll
        for (int i = 0; i < 4; i++) acc[g][i] = 0.f;

    for (int a = 0; a < AA; a++) {
        const int sa = s * AA + a;
        if (!g_mask[sa]) continue;
        __syncthreads();                 // prior expert's smem reads done

        // ---- stage weights via cp.async (3 groups) -----------------------
        {
            const char* g1 = (const char*)(g_w1img + (size_t)sa * 34816);
            for (int i = tid; i < 2176; i += 128)
                CP16(smb + OFF_W1 + i * 16, g1 + i * 16);
            const char* gb = (const char*)(g_bias + sa * 256);
            if (tid < 64)
                CP16(smb + OFF_BIAS + tid * 16, gb + tid * 16);
            CP_COMMIT();
            const char* g2 = (const char*)(g_w2img + (size_t)sa * 18432);
            for (int i = tid; i < 1152; i += 128)
                CP16(smb + OFF_W2 + i * 16, g2 + i * 16);
            CP_COMMIT();
            const char* g3 = (const char*)(g_w3img + (size_t)sa * 36864);
            for (int i = tid; i < 2304; i += 128)
                CP16(smb + OFF_W3 + i * 16, g3 + i * 16);
            CP_COMMIT();
        }

        // X fragment base pointers for this (a)
        const unsigned short* pxh_lo = g_xhi + ((size_t)r_lo * AA + a) * DAZ;
        const unsigned short* pxh_hi = pxh_lo + (size_t)8 * AA * DAZ;
        const unsigned short* pxl_lo = g_xlo + ((size_t)r_lo * AA + a) * DAZ;
        const unsigned short* pxl_hi = pxl_lo + (size_t)8 * AA * DAZ;

        unsigned xc[8], xn[8];
        {   // prefetch kt=0 while W1 copies land
            int k = kb;
            xc[0] = *(const unsigned*)(pxh_lo + k);
            xc[1] = *(const unsigned*)(pxh_hi + k);
            xc[2] = *(const unsigned*)(pxh_lo + k + 8);
            xc[3] = *(const unsigned*)(pxh_hi + k + 8);
            xc[4] = *(const unsigned*)(pxl_lo + k);
            xc[5] = *(const unsigned*)(pxl_hi + k);
            xc[6] = *(const unsigned*)(pxl_lo + k + 8);
            xc[7] = *(const unsigned*)(pxl_hi + k + 8);
        }

        CP_WAIT(2);
        __syncthreads();                 // W1 + bias visible

        // ---- L1: C1[16x64] = Xsplit @ W1split ----------------------------
        float C1[8][4];
        #pragma unroll
        for (int nt = 0; nt < 8; nt++)
            #pragma unroll
            for (int i = 0; i < 4; i++) C1[nt][i] = 0.f;

        #pragma unroll
        for (int kt = 0; kt < 8; kt++) {
            if (kt < 7) {
                int k = (kt + 1) * 16 + kb;
                xn[0] = *(const unsigned*)(pxh_lo + k);
                xn[1] = *(const unsigned*)(pxh_hi + k);
                xn[2] = *(const unsigned*)(pxh_lo + k + 8);
                xn[3] = *(const unsigned*)(pxh_hi + k + 8);
                xn[4] = *(const unsigned*)(pxl_lo + k);
                xn[5] = *(const unsigned*)(pxl_hi + k);
                xn[6] = *(const unsigned*)(pxl_lo + k + 8);
                xn[7] = *(const unsigned*)(pxl_hi + k + 8);
            }
            #pragma unroll
            for (int np = 0; np < 4; np++) {
                unsigned bh[4], bl[4];
                uint32_t ad = w1b + (unsigned)(np * 16 + rowadj) * 272 + kt * 32 + coladj;
                ldsm4(bh, ad);
                ldsm4(bl, ad + 17408);
                mma_bf16(C1[2 * np],     xc,     bh);
                mma_bf16(C1[2 * np],     xc + 4, bh);
                mma_bf16(C1[2 * np],     xc,     bl);
                mma_bf16(C1[2 * np + 1], xc,     bh + 2);
                mma_bf16(C1[2 * np + 1], xc + 4, bh + 2);
                mma_bf16(C1[2 * np + 1], xc,     bl + 2);
            }
            if (kt < 7) {
                #pragma unroll
                for (int j = 0; j < 8; j++) xc[j] = xn[j];
            }
        }

        // ---- E1: relu+bias, resplit -> A2 fragments (registers only) -----
        unsigned a2h[4][4], a2l[4][4];
        #pragma unroll
        for (int nt = 0; nt < 8; nt++) {
            float2 be = *(const float2*)(sBias + nt * 8 + kb);
            float h0 = fmaxf(C1[nt][0] + be.x, 0.f);
            float h1 = fmaxf(C1[nt][1] + be.y, 0.f);
            float h2 = fmaxf(C1[nt][2] + be.x, 0.f);
            float h3 = fmaxf(C1[nt][3] + be.y, 0.f);
            unsigned short h0h = f2bf(h0), h1h = f2bf(h1), h2h = f2bf(h2), h3h = f2bf(h3);
            int kt = nt >> 1, hf = (nt & 1) * 2;
            a2h[kt][hf]     = packbf(h0h, h1h);
            a2h[kt][hf + 1] = packbf(h2h, h3h);
            a2l[kt][hf]     = packbf(f2bf(h0 - bf2f(h0h)), f2bf(h1 - bf2f(h1h)));
            a2l[kt][hf + 1] = packbf(f2bf(h2 - bf2f(h2h)), f2bf(h3 - bf2f(h3h)));
        }

        CP_WAIT(1);
        __syncthreads();                 // W2 visible

        // ---- L2: C2[16x64] = H1split @ W2split ---------------------------
        float C2[8][4];
        #pragma unroll
        for (int nt = 0; nt < 8; nt++)
            #pragma unroll
            for (int i = 0; i < 4; i++) C2[nt][i] = 0.f;

        #pragma unroll
        for (int kt = 0; kt < 4; kt++) {
            #pragma unroll
            for (int np = 0; np < 4; np++) {
                unsigned bh[4], bl[4];
                uint32_t ad = w2b + (unsigned)(np * 16 + rowadj) * 144 + kt * 32 + coladj;
                ldsm4(bh, ad);
                ldsm4(bl, ad + 9216);
                mma_bf16(C2[2 * np],     a2h[kt], bh);
                mma_bf16(C2[2 * np],     a2l[kt], bh);
                mma_bf16(C2[2 * np],     a2h[kt], bl);
                mma_bf16(C2[2 * np + 1], a2h[kt], bh + 2);
                mma_bf16(C2[2 * np + 1], a2l[kt], bh + 2);
                mma_bf16(C2[2 * np + 1], a2h[kt], bl + 2);
            }
        }

        // ---- E2 -> A3 fragments ------------------------------------------
        unsigned a3h[4][4], a3l[4][4];
        #pragma unroll
        for (int nt = 0; nt < 8; nt++) {
            float2 be = *(const float2*)(sBias + 64 + nt * 8 + kb);
            float h0 = fmaxf(C2[nt][0] + be.x, 0.f);
            float h1 = fmaxf(C2[nt][1] + be.y, 0.f);
            float h2 = fmaxf(C2[nt][2] + be.x, 0.f);
            float h3 = fmaxf(C2[nt][3] + be.y, 0.f);
            unsigned short h0h = f2bf(h0), h1h = f2bf(h1), h2h = f2bf(h2), h3h = f2bf(h3);
            int kt = nt >> 1, hf = (nt & 1) * 2;
            a3h[kt][hf]     = packbf(h0h, h1h);
            a3h[kt][hf + 1] = packbf(h2h, h3h);
            a3l[kt][hf]     = packbf(f2bf(h0 - bf2f(h0h)), f2bf(h1 - bf2f(h1h)));
            a3l[kt][hf + 1] = packbf(f2bf(h2 - bf2f(h2h)), f2bf(h3 - bf2f(h3h)));
        }

        CP_WAIT(0);
        __syncthreads();                 // W3 visible

        // ---- L3 (two N-halves of 64): acc += relu(H2split @ W3split + b3)
        #pragma unroll
        for (int half = 0; half < 2; half++) {
            float C3[8][4];
            #pragma unroll
            for (int nt = 0; nt < 8; nt++)
                #pragma unroll
                for (int i = 0; i < 4; i++) C3[nt][i] = 0.f;

            #pragma unroll
            for (int kt = 0; kt < 4; kt++) {
                #pragma unroll
                for (int np = 0; np < 4; np++) {
                    unsigned bh[4], bl[4];
                    uint32_t ad = w3b + (unsigned)(half * 64 + np * 16 + rowadj) * 144
                                      + kt * 32 + coladj;
                    ldsm4(bh, ad);
                    ldsm4(bl, ad + 18432);
                    mma_bf16(C3[2 * np],     a3h[kt], bh);
                    mma_bf16(C3[2 * np],     a3l[kt], bh);
                    mma_bf16(C3[2 * np],     a3h[kt], bl);
                    mma_bf16(C3[2 * np + 1], a3h[kt], bh + 2);
                    mma_bf16(C3[2 * np + 1], a3l[kt], bh + 2);
                    mma_bf16(C3[2 * np + 1], a3h[kt], bl + 2);
                }
            }
            #pragma unroll
            for (int nt = 0; nt < 8; nt++) {
                int g = half * 8 + nt;
                float2 be = *(const float2*)(sBias + 128 + g * 8 + kb);
                acc[g][0] += fmaxf(C3[nt][0] + be.x, 0.f);
                acc[g][1] += fmaxf(C3[nt][1] + be.y, 0.f);
                acc[g][2] += fmaxf(C3[nt][2] + be.x, 0.f);
                acc[g][3] += fmaxf(C3[nt][3] + be.y, 0.f);
            }
        }
    }

    // ---- final: out = state + diff ---------------------------------------
    #pragma unroll
    for (int g = 0; g < 16; g++) {
        int e = g * 8 + kb;
        size_t i1 = ((size_t)r_lo * SS + s) * DSZ + e;
        size_t i2 = i1 + (size_t)8 * SS * DSZ;
        float2 s1 = *(const float2*)(state + i1);
        float2 s2 = *(const float2*)(state + i2);
        float2 o1 = {s1.x + acc[g][0], s1.y + acc[g][1]};
        float2 o2 = {s2.x + acc[g][2], s2.y + acc[g][3]};
        *(float2*)(out + i1) = o1;
        *(float2*)(out + i2) = o2;
    }
}

// ---------------- launcher -------------------------------------------------
extern "C" void kernel_launch(void* const* d_in, const int* in_sizes, int n_in,
                              void* d_out, int out_size) {
    const float* state = (const float*)d_in[0];
    const float* act   = (const float*)d_in[1];
    const unsigned char* mask_raw = (const unsigned char*)d_in[2];
    const float* W1 = (const float*)d_in[3];
    const float* b1 = (const float*)d_in[4];
    const float* W2 = (const float*)d_in[5];
    const float* b2 = (const float*)d_in[6];
    const float* W3 = (const float*)d_in[7];
    const float* b3 = (const float*)d_in[8];
    float* out = (float*)d_out;
    (void)in_sizes; (void)n_in; (void)out_size;

    build_mask_kernel<<<1, 32>>>(mask_raw);
    conv_x_kernel<<<(BB * AA * DAZ / 8) / 256, 256>>>(act);
    conv_w_kernel<<<SS * AA, 128>>>(W1, W2, W3, b1, b2, b3);

    cudaFuncSetAttribute(intervention_hmma_kernel,
                         cudaFuncAttributeMaxDynamicSharedMemorySize, SMEM_MAIN);
    dim3 grid(BB / BT, SS);
    intervention_hmma_kernel<<<grid, 128, SMEM_MAIN>>>(state, out);
}

// round 14
// speedup vs baseline: 4.6069x; 1.1692x over previous
#include <cuda_runtime.h>
#include <cstdint>

#define BB   2048
#define SS   16
#define AA   16
#define DSZ  128
#define DAZ  128
#define HH   64
#define BT   64

// ---------------- global bf16 images (prologue output) ---------------------
__device__ __align__(16) unsigned short g_xhi[BB * AA * DAZ];
__device__ __align__(16) unsigned short g_xlo[BB * AA * DAZ];
// W1: [2 planes][64 n][136 k] (34816 B/sa), W2: [2][64][72] (18432 B),
// W3: [2][128][72] (36864 B). hi plane first, lo at +plane_bytes.
__device__ __align__(16) unsigned char g_w1img[SS * AA * 34816];
__device__ __align__(16) unsigned char g_w2img[SS * AA * 18432];
__device__ __align__(16) unsigned char g_w3img[SS * AA * 36864];
__device__ __align__(16) float g_bias[SS * AA * 256];   // [0,64):b1 [64,128):b2 [128,256):b3
__device__ int g_mask[SS * AA];

// ---------------- helpers ---------------------------------------------------
static __device__ __forceinline__ uint32_t smem_u32(const void* p) {
    uint32_t a;
    asm("{ .reg .u64 t; cvta.to.shared.u64 t, %1; cvt.u32.u64 %0, t; }" : "=r"(a) : "l"(p));
    return a;
}
// split two floats into packed bf16 hi-pair and lo-pair (lo element in low 16)
static __device__ __forceinline__ void split2(float x0, float x1, unsigned& hi, unsigned& lo) {
    asm("cvt.rn.bf16x2.f32 %0, %1, %2;" : "=r"(hi) : "f"(x1), "f"(x0));
    float f0 = __uint_as_float(hi << 16);
    float f1 = __uint_as_float(hi & 0xffff0000u);
    asm("cvt.rn.bf16x2.f32 %0, %1, %2;" : "=r"(lo) : "f"(x1 - f1), "f"(x0 - f0));
}
// D += A x B  (m16n8k16, bf16 in, f32 acc)
static __device__ __forceinline__ void mma_bf16(float* c, const unsigned* a, const unsigned* b) {
    asm volatile("mma.sync.aligned.m16n8k16.row.col.f32.bf16.bf16.f32 "
                 "{%0,%1,%2,%3}, {%4,%5,%6,%7}, {%8,%9}, {%0,%1,%2,%3};"
                 : "+f"(c[0]), "+f"(c[1]), "+f"(c[2]), "+f"(c[3])
                 : "r"(a[0]), "r"(a[1]), "r"(a[2]), "r"(a[3]), "r"(b[0]), "r"(b[1]));
}
static __device__ __forceinline__ void ldsm4(unsigned* r, uint32_t addr) {
    asm volatile("ldmatrix.sync.aligned.m8n8.x4.shared.b16 {%0,%1,%2,%3}, [%4];"
                 : "=r"(r[0]), "=r"(r[1]), "=r"(r[2]), "=r"(r[3]) : "r"(addr));
}
#define CP16(sdst, gsrc) asm volatile("cp.async.cg.shared.global [%0], [%1], 16;" :: "r"(sdst), "l"(gsrc))
#define CP_COMMIT()      asm volatile("cp.async.commit_group;" ::: "memory")
#define CP_WAIT(n)       asm volatile("cp.async.wait_group %0;" :: "n"(n) : "memory")

// ---------------- fused prologue -------------------------------------------
// blocks [0,2048): X convert; [2048,2304): weights for sa=bx-2048; [2304]: mask
#define NX_BLK 2048
#define NW_BLK 256

__global__ void __launch_bounds__(256) prep_kernel(const float* __restrict__ act,
                                                   const float* __restrict__ W1g,
                                                   const float* __restrict__ W2g,
                                                   const float* __restrict__ W3g,
                                                   const float* __restrict__ b1g,
                                                   const float* __restrict__ b2g,
                                                   const float* __restrict__ b3g,
                                                   const unsigned char* __restrict__ raw) {
    const int bx = blockIdx.x;
    const int tid = threadIdx.x;

    if (bx < NX_BLK) {
        // ---- X -> bf16 hi/lo planes ----
        size_t idx = ((size_t)bx * 256 + tid) * 8;
        float4 v0 = *(const float4*)(act + idx);
        float4 v1 = *(const float4*)(act + idx + 4);
        uint4 qh, ql;
        split2(v0.x, v0.y, qh.x, ql.x);
        split2(v0.z, v0.w, qh.y, ql.y);
        split2(v1.x, v1.y, qh.z, ql.z);
        split2(v1.z, v1.w, qh.w, ql.w);
        *(uint4*)(g_xhi + idx) = qh;
        *(uint4*)(g_xlo + idx) = ql;
        return;
    }
    if (bx < NX_BLK + NW_BLK) {
        const int sa = bx - NX_BLK;
        // ---- W1 [128 k][64 n] -> [64 n][136 k] hi/lo ----
        {
            const float* w = W1g + (size_t)sa * (DAZ * HH);
            unsigned char* img = g_w1img + (size_t)sa * 34816;
            for (int i = tid; i < 16 * 64; i += 256) {
                int c8 = i >> 6, n = i & 63;
                float x[8];
                #pragma unroll
                for (int j = 0; j < 8; j++) x[j] = w[(c8 * 8 + j) * HH + n];
                uint4 qh, ql;
                split2(x[0], x[1], qh.x, ql.x);
                split2(x[2], x[3], qh.y, ql.y);
                split2(x[4], x[5], qh.z, ql.z);
                split2(x[6], x[7], qh.w, ql.w);
                *(uint4*)(img + n * 272 + c8 * 16)         = qh;
                *(uint4*)(img + 17408 + n * 272 + c8 * 16) = ql;
            }
        }
        // ---- W2 [64 k][64 n] -> [64 n][72 k] hi/lo ----
        {
            const float* w = W2g + (size_t)sa * (HH * HH);
            unsigned char* img = g_w2img + (size_t)sa * 18432;
            for (int i = tid; i < 8 * 64; i += 256) {
                int c8 = i >> 6, n = i & 63;
                float x[8];
                #pragma unroll
                for (int j = 0; j < 8; j++) x[j] = w[(c8 * 8 + j) * HH + n];
                uint4 qh, ql;
                split2(x[0], x[1], qh.x, ql.x);
                split2(x[2], x[3], qh.y, ql.y);
                split2(x[4], x[5], qh.z, ql.z);
                split2(x[6], x[7], qh.w, ql.w);
                *(uint4*)(img + n * 144 + c8 * 16)        = qh;
                *(uint4*)(img + 9216 + n * 144 + c8 * 16) = ql;
            }
        }
        // ---- W3 [64 k][128 n] -> [128 n][72 k] hi/lo ----
        {
            const float* w = W3g + (size_t)sa * (HH * DSZ);
            unsigned char* img = g_w3img + (size_t)sa * 36864;
            for (int i = tid; i < 8 * 128; i += 256) {
                int c8 = i >> 7, n = i & 127;
                float x[8];
                #pragma unroll
                for (int j = 0; j < 8; j++) x[j] = w[(c8 * 8 + j) * DSZ + n];
                uint4 qh, ql;
                split2(x[0], x[1], qh.x, ql.x);
                split2(x[2], x[3], qh.y, ql.y);
                split2(x[4], x[5], qh.z, ql.z);
                split2(x[6], x[7], qh.w, ql.w);
                *(uint4*)(img + n * 144 + c8 * 16)         = qh;
                *(uint4*)(img + 18432 + n * 144 + c8 * 16) = ql;
            }
        }
        // ---- biases ----
        if (tid < 64) {
            g_bias[sa * 256 + tid]      = b1g[(size_t)sa * HH + tid];
            g_bias[sa * 256 + 64 + tid] = b2g[(size_t)sa * HH + tid];
        }
        if (tid < 128)
            g_bias[sa * 256 + 128 + tid] = b3g[(size_t)sa * DSZ + tid];
        return;
    }
    // ---- mask sniff (bool / int32 / float32 robust) ----
    if (tid != 0) return;
    bool off_zero = true;
    for (int i = 0; i < SS * AA; i++)
        if ((i & 3) && raw[i]) { off_zero = false; break; }
    if (off_zero) {
        const int* p = (const int*)raw;
        for (int i = 0; i < SS * AA; i++) g_mask[i] = (p[i] != 0);
        return;
    }
    const unsigned int* f = (const unsigned int*)raw;
    bool isf = true;
    for (int i = 0; i < 64; i++) {
        unsigned v = f[i];
        if (v != 0u && v != 0x3f800000u) { isf = false; break; }
    }
    if (isf) {
        for (int i = 0; i < SS * AA; i++) g_mask[i] = (f[i] != 0u);
        return;
    }
    for (int i = 0; i < SS * AA; i++) g_mask[i] = (raw[i] != 0);
}

// ---------------- main kernel ----------------------------------------------
#define OFF_W1    0
#define OFF_W2    34816
#define OFF_W3    53248
#define OFF_BIAS  90112     // 2 x 1024 B (double buffered)
#define OFF_ALIST 92160     // 16 ints + count
#define SMEM_MAIN 92288

__global__ void __launch_bounds__(128, 2)
intervention_hmma_kernel(const float* __restrict__ state,
                         float* __restrict__ out) {
    extern __shared__ char sm[];
    const uint32_t smb = smem_u32(sm);

    const int tid  = threadIdx.x;
    const int warp = tid >> 5;
    const int lane = tid & 31;
    const int s    = blockIdx.y;
    const int b0   = blockIdx.x * BT;

    const int rowbase = warp * 16;
    const int kb      = (lane & 3) * 2;
    const int rowadj  = (lane & 7) + ((lane & 16) ? 8 : 0);
    const int coladj  = (lane & 8) ? 16 : 0;
    const int r_lo    = b0 + rowbase + (lane >> 2);
    const uint32_t w1b = smb + OFF_W1;
    const uint32_t w2b = smb + OFF_W2;
    const uint32_t w3b = smb + OFF_W3;

    // ---- build active-expert list (uniform per CTA) ----------------------
    int* al = (int*)(sm + OFF_ALIST);
    if (tid == 0) {
        int n = 0;
        for (int a = 0; a < AA; a++)
            if (g_mask[s * AA + a]) al[n++] = a;
        al[16] = n;
    }
    __syncthreads();
    const int nact = al[16];

    float acc[16][4];
    #pragma unroll
    for (int g = 0; g < 16; g++)
        #pragma unroll
        for (int i = 0; i < 4; i++) acc[g][i] = 0.f;

    if (nact > 0) {
        // prologue: G1 = W1(e0)+bias(e0->buf0), G2 = W2(e0)
        const int sa0 = s * AA + al[0];
        {
            const char* g1 = (const char*)(g_w1img + (size_t)sa0 * 34816);
            for (int i = tid; i < 2176; i += 128) CP16(smb + OFF_W1 + i * 16, g1 + i * 16);
            const char* gb = (const char*)(g_bias + sa0 * 256);
            if (tid < 64) CP16(smb + OFF_BIAS + tid * 16, gb + tid * 16);
        }
        CP_COMMIT();
        {
            const char* g2 = (const char*)(g_w2img + (size_t)sa0 * 18432);
            for (int i = tid; i < 1152; i += 128) CP16(smb + OFF_W2 + i * 16, g2 + i * 16);
        }
        CP_COMMIT();

        for (int i = 0; i < nact; i++) {
            const int e   = al[i];
            const int sa  = s * AA + e;
            const int nx  = al[(i + 1 < nact) ? i + 1 : i];
            const int san = s * AA + nx;
            const int bufc = i & 1, bufn = (i + 1) & 1;
            const float* sB = (const float*)(sm + OFF_BIAS + bufc * 1024);

            // step 1: W1(e)+bias(e) landed; prior W3 readers done; commit W3(e)
            CP_WAIT(1);
            __syncthreads();
            {
                const char* g3 = (const char*)(g_w3img + (size_t)sa * 36864);
                for (int j = tid; j < 2304; j += 128) CP16(smb + OFF_W3 + j * 16, g3 + j * 16);
            }
            CP_COMMIT();

            // X fragment base pointers for this (e)
            const unsigned short* pxh_lo = g_xhi + ((size_t)r_lo * AA + e) * DAZ;
            const unsigned short* pxh_hi = pxh_lo + (size_t)8 * AA * DAZ;
            const unsigned short* pxl_lo = g_xlo + ((size_t)r_lo * AA + e) * DAZ;
            const unsigned short* pxl_hi = pxl_lo + (size_t)8 * AA * DAZ;

            unsigned xc[8], xn[8];
            {
                int k = kb;
                xc[0] = *(const unsigned*)(pxh_lo + k);
                xc[1] = *(const unsigned*)(pxh_hi + k);
                xc[2] = *(const unsigned*)(pxh_lo + k + 8);
                xc[3] = *(const unsigned*)(pxh_hi + k + 8);
                xc[4] = *(const unsigned*)(pxl_lo + k);
                xc[5] = *(const unsigned*)(pxl_hi + k);
                xc[6] = *(const unsigned*)(pxl_lo + k + 8);
                xc[7] = *(const unsigned*)(pxl_hi + k + 8);
            }

            // ---- L1: C1[16x64] = Xsplit @ W1split ------------------------
            float C1[8][4];
            #pragma unroll
            for (int nt = 0; nt < 8; nt++)
                #pragma unroll
                for (int q = 0; q < 4; q++) C1[nt][q] = 0.f;

            #pragma unroll
            for (int kt = 0; kt < 8; kt++) {
                if (kt < 7) {
                    int k = (kt + 1) * 16 + kb;
                    xn[0] = *(const unsigned*)(pxh_lo + k);
                    xn[1] = *(const unsigned*)(pxh_hi + k);
                    xn[2] = *(const unsigned*)(pxh_lo + k + 8);
                    xn[3] = *(const unsigned*)(pxh_hi + k + 8);
                    xn[4] = *(const unsigned*)(pxl_lo + k);
                    xn[5] = *(const unsigned*)(pxl_hi + k);
                    xn[6] = *(const unsigned*)(pxl_lo + k + 8);
                    xn[7] = *(const unsigned*)(pxl_hi + k + 8);
                }
                #pragma unroll
                for (int np = 0; np < 4; np++) {
                    unsigned bh[4], bl[4];
                    uint32_t ad = w1b + (unsigned)(np * 16 + rowadj) * 272 + kt * 32 + coladj;
                    ldsm4(bh, ad);
                    ldsm4(bl, ad + 17408);
                    mma_bf16(C1[2 * np],     xc,     bh);
                    mma_bf16(C1[2 * np],     xc + 4, bh);
                    mma_bf16(C1[2 * np],     xc,     bl);
                    mma_bf16(C1[2 * np + 1], xc,     bh + 2);
                    mma_bf16(C1[2 * np + 1], xc + 4, bh + 2);
                    mma_bf16(C1[2 * np + 1], xc,     bl + 2);
                }
                if (kt < 7) {
                    #pragma unroll
                    for (int j = 0; j < 8; j++) xc[j] = xn[j];
                }
            }

            // ---- E1: relu+bias -> A2 fragments ---------------------------
            unsigned a2h[4][4], a2l[4][4];
            #pragma unroll
            for (int nt = 0; nt < 8; nt++) {
                float2 be = *(const float2*)(sB + nt * 8 + kb);
                float h0 = fmaxf(C1[nt][0] + be.x, 0.f);
                float h1 = fmaxf(C1[nt][1] + be.y, 0.f);
                float h2 = fmaxf(C1[nt][2] + be.x, 0.f);
                float h3 = fmaxf(C1[nt][3] + be.y, 0.f);
                int kt = nt >> 1, hf = (nt & 1) * 2;
                split2(h0, h1, a2h[kt][hf],     a2l[kt][hf]);
                split2(h2, h3, a2h[kt][hf + 1], a2l[kt][hf + 1]);
            }

            // step 3: W2(e) landed; W1 readers done; commit W1(nx)+bias(nx)
            CP_WAIT(1);
            __syncthreads();
            {
                const char* g1 = (const char*)(g_w1img + (size_t)san * 34816);
                for (int j = tid; j < 2176; j += 128) CP16(smb + OFF_W1 + j * 16, g1 + j * 16);
                const char* gb = (const char*)(g_bias + san * 256);
                if (tid < 64) CP16(smb + OFF_BIAS + bufn * 1024 + tid * 16, gb + tid * 16);
            }
            CP_COMMIT();

            // ---- L2 ------------------------------------------------------
            float C2[8][4];
            #pragma unroll
            for (int nt = 0; nt < 8; nt++)
                #pragma unroll
                for (int q = 0; q < 4; q++) C2[nt][q] = 0.f;

            #pragma unroll
            for (int kt = 0; kt < 4; kt++) {
                #pragma unroll
                for (int np = 0; np < 4; np++) {
                    unsigned bh[4], bl[4];
                    uint32_t ad = w2b + (unsigned)(np * 16 + rowadj) * 144 + kt * 32 + coladj;
                    ldsm4(bh, ad);
                    ldsm4(bl, ad + 9216);
                    mma_bf16(C2[2 * np],     a2h[kt], bh);
                    mma_bf16(C2[2 * np],     a2l[kt], bh);
                    mma_bf16(C2[2 * np],     a2h[kt], bl);
                    mma_bf16(C2[2 * np + 1], a2h[kt], bh + 2);
                    mma_bf16(C2[2 * np + 1], a2l[kt], bh + 2);
                    mma_bf16(C2[2 * np + 1], a2h[kt], bl + 2);
                }
            }

            // ---- E2 -> A3 fragments --------------------------------------
            unsigned a3h[4][4], a3l[4][4];
            #pragma unroll
            for (int nt = 0; nt < 8; nt++) {
                float2 be = *(const float2*)(sB + 64 + nt * 8 + kb);
                float h0 = fmaxf(C2[nt][0] + be.x, 0.f);
                float h1 = fmaxf(C2[nt][1] + be.y, 0.f);
                float h2 = fmaxf(C2[nt][2] + be.x, 0.f);
                float h3 = fmaxf(C2[nt][3] + be.y, 0.f);
                int kt = nt >> 1, hf = (nt & 1) * 2;
                split2(h0, h1, a3h[kt][hf],     a3l[kt][hf]);
                split2(h2, h3, a3h[kt][hf + 1], a3l[kt][hf + 1]);
            }

            // step 5: W3(e) landed; W2 readers done; commit W2(nx)
            CP_WAIT(1);
            __syncthreads();
            {
                const char* g2 = (const char*)(g_w2img + (size_t)san * 18432);
                for (int j = tid; j < 1152; j += 128) CP16(smb + OFF_W2 + j * 16, g2 + j * 16);
            }
            CP_COMMIT();

            // ---- L3 + E3 -------------------------------------------------
            #pragma unroll
            for (int half = 0; half < 2; half++) {
                float C3[8][4];
                #pragma unroll
                for (int nt = 0; nt < 8; nt++)
                    #pragma unroll
                    for (int q = 0; q < 4; q++) C3[nt][q] = 0.f;

                #pragma unroll
                for (int kt = 0; kt < 4; kt++) {
                    #pragma unroll
                    for (int np = 0; np < 4; np++) {
                        unsigned bh[4], bl[4];
                        uint32_t ad = w3b + (unsigned)(half * 64 + np * 16 + rowadj) * 144
                                          + kt * 32 + coladj;
                        ldsm4(bh, ad);
                        ldsm4(bl, ad + 18432);
                        mma_bf16(C3[2 * np],     a3h[kt], bh);
                        mma_bf16(C3[2 * np],     a3l[kt], bh);
                        mma_bf16(C3[2 * np],     a3h[kt], bl);
                        mma_bf16(C3[2 * np + 1], a3h[kt], bh + 2);
                        mma_bf16(C3[2 * np + 1], a3l[kt], bh + 2);
                        mma_bf16(C3[2 * np + 1], a3h[kt], bl + 2);
                    }
                }
                #pragma unroll
                for (int nt = 0; nt < 8; nt++) {
                    int g = half * 8 + nt;
                    float2 be = *(const float2*)(sB + 128 + g * 8 + kb);
                    acc[g][0] += fmaxf(C3[nt][0] + be.x, 0.f);
                    acc[g][1] += fmaxf(C3[nt][1] + be.y, 0.f);
                    acc[g][2] += fmaxf(C3[nt][2] + be.x, 0.f);
                    acc[g][3] += fmaxf(C3[nt][3] + be.y, 0.f);
                }
            }
        }
    }

    // ---- final: out = state + diff ---------------------------------------
    #pragma unroll
    for (int g = 0; g < 16; g++) {
        int e = g * 8 + kb;
        size_t i1 = ((size_t)r_lo * SS + s) * DSZ + e;
        size_t i2 = i1 + (size_t)8 * SS * DSZ;
        float2 s1 = *(const float2*)(state + i1);
        float2 s2 = *(const float2*)(state + i2);
        float2 o1 = {s1.x + acc[g][0], s1.y + acc[g][1]};
        float2 o2 = {s2.x + acc[g][2], s2.y + acc[g][3]};
        *(float2*)(out + i1) = o1;
        *(float2*)(out + i2) = o2;
    }
}

// ---------------- launcher -------------------------------------------------
extern "C" void kernel_launch(void* const* d_in, const int* in_sizes, int n_in,
                              void* d_out, int out_size) {
    const float* state = (const float*)d_in[0];
    const float* act   = (const float*)d_in[1];
    const unsigned char* mask_raw = (const unsigned char*)d_in[2];
    const float* W1 = (const float*)d_in[3];
    const float* b1 = (const float*)d_in[4];
    const float* W2 = (const float*)d_in[5];
    const float* b2 = (const float*)d_in[6];
    const float* W3 = (const float*)d_in[7];
    const float* b3 = (const float*)d_in[8];
    float* out = (float*)d_out;
    (void)in_sizes; (void)n_in; (void)out_size;

    prep_kernel<<<NX_BLK + NW_BLK + 1, 256>>>(act, W1, W2, W3, b1, b2, b3, mask_raw);

    cudaFuncSetAttribute(intervention_hmma_kernel,
                         cudaFuncAttributeMaxDynamicSharedMemorySize, SMEM_MAIN);
    dim3 grid(BB / BT, SS);
    intervention_hmma_kernel<<<grid, 128, SMEM_MAIN>>>(state, out);
}